// round 1
// baseline (speedup 1.0000x reference)
#include <cuda_runtime.h>
#include <math.h>

// Problem shapes (fixed by the dataset)
#define Bk 8
#define Lk 2048
#define Dk 2048
#define Rk 256
#define BLk (Bk * Lk)   // 16384 rows

// ---------------- device scratch (static allocation only) ----------------
static __device__ float g_E[Rk * Rk];          // E = T @ dlt_T              (256x256)
static __device__ float g_Ap[Dk * Rk];         // A' = gamma ⊙ (P @ E^T)     (2048x256)
static __device__ float g_U[(size_t)BLk * Rk]; // z_mixed                    (16384x256)
static __device__ float g_rstd[BLk];
static __device__ float g_nmr[BLk];            // -mean*rstd per row
static __device__ float g_feat[BLk];
static __device__ float g_pg[Rk], g_pb[Rk];    // gamma^T P, beta^T P
static __device__ float g_cA[Rk], g_cB[Rk];
static __device__ float g_G[Dk];               // g_sigmoid[d] * scale[d]
static __device__ float g_consts[4];           // {sum gamma, sum beta, sum phi_w}
static __device__ float g_pgp[32 * Rk], g_pbp[32 * Rk];

__device__ __forceinline__ float blockReduce256(float v, float* sm) {
    int t = threadIdx.x;
    sm[t] = v;
    __syncthreads();
    #pragma unroll
    for (int off = 128; off > 0; off >>= 1) {
        if (t < off) sm[t] += sm[t + off];
        __syncthreads();
    }
    float r = sm[0];
    __syncthreads();
    return r;
}

// ---------------- tiny precompute kernels ----------------

// sums of gamma, beta, phi_w
__global__ void kConst(const float* __restrict__ gamma, const float* __restrict__ beta,
                       const float* __restrict__ phiw) {
    __shared__ float sm[256];
    int t = threadIdx.x;
    float a = 0.f, b = 0.f, c = 0.f;
    for (int j = t; j < Dk; j += 256) { a += gamma[j]; b += beta[j]; }
    for (int j = t; j < Rk; j += 256) { c += phiw[j]; }
    float A = blockReduce256(a, sm);
    float B = blockReduce256(b, sm);
    float C = blockReduce256(c, sm);
    if (t == 0) { g_consts[0] = A; g_consts[1] = B; g_consts[2] = C; }
}

// partial pg[r] = sum_d gamma_d P[d,r], pb likewise (32 d-chunks of 64)
__global__ void kPgb1(const float* __restrict__ P, const float* __restrict__ gamma,
                      const float* __restrict__ beta) {
    int r = threadIdx.x;
    int chunk = blockIdx.x;
    float ag = 0.f, ab = 0.f;
    #pragma unroll 4
    for (int j = 0; j < 64; j++) {
        int d = chunk * 64 + j;
        float p = P[(size_t)d * Rk + r];
        ag += gamma[d] * p;
        ab += beta[d] * p;
    }
    g_pgp[chunk * Rk + r] = ag;
    g_pbp[chunk * Rk + r] = ab;
}

__global__ void kPgb2() {
    int r = threadIdx.x;
    float a = 0.f, b = 0.f;
    #pragma unroll
    for (int c = 0; c < 32; c++) { a += g_pgp[c * Rk + r]; b += g_pbp[c * Rk + r]; }
    g_pg[r] = a;
    g_pb[r] = b;
}

// E[s,r] = sum_i toep[i-s+pad] * dlt[i,r]   (cross-correlation, SAME padding)
// also cA[s] = sum_r pg[r] E[s,r], cB[s] = sum_r pb[r] E[s,r]
__global__ void kE(const float* __restrict__ dlt, const float* __restrict__ toep, int Kc) {
    __shared__ float st[Rk];
    __shared__ float red[256];
    int s = blockIdx.x;
    int r = threadIdx.x;
    int pad = (Kc - 1) / 2;
    if (r < Kc) st[r] = toep[r];
    __syncthreads();
    int lo = s - pad; if (lo < 0) lo = 0;
    int hi = s - pad + Kc - 1; if (hi > Rk - 1) hi = Rk - 1;
    float e = 0.f;
    for (int i = lo; i <= hi; i++) e += st[i - s + pad] * dlt[(size_t)i * Rk + r];
    g_E[(size_t)s * Rk + r] = e;
    float ca = blockReduce256(g_pg[r] * e, red);
    float cb = blockReduce256(g_pb[r] * e, red);
    if (r == 0) { g_cA[s] = ca; g_cB[s] = cb; }
}

// A'[d,s] = gamma[d] * sum_r P[d,r] E[s,r]    (64x64 tiles, 4x4 per thread)
__global__ __launch_bounds__(256) void kAp(const float* __restrict__ P,
                                           const float* __restrict__ gamma) {
    __shared__ float Ps[16][64];
    __shared__ float Es[16][64];
    int dBase = blockIdx.y * 64, sBase = blockIdx.x * 64;
    int t = threadIdx.x;
    int ty = t >> 4, tx = t & 15;
    float acc[4][4] = {};
    for (int k0 = 0; k0 < Rk; k0 += 16) {
        {
            int m = t >> 2, kq = (t & 3) * 4;
            float4 v = *(const float4*)&P[(size_t)(dBase + m) * Rk + k0 + kq];
            Ps[kq + 0][m] = v.x; Ps[kq + 1][m] = v.y; Ps[kq + 2][m] = v.z; Ps[kq + 3][m] = v.w;
        }
        {
            int n = t >> 2, kq = (t & 3) * 4;
            float4 v = *(const float4*)&g_E[(size_t)(sBase + n) * Rk + k0 + kq];
            Es[kq + 0][n] = v.x; Es[kq + 1][n] = v.y; Es[kq + 2][n] = v.z; Es[kq + 3][n] = v.w;
        }
        __syncthreads();
        #pragma unroll
        for (int k = 0; k < 16; k++) {
            float a[4], b[4];
            #pragma unroll
            for (int i = 0; i < 4; i++) a[i] = Ps[k][ty * 4 + i];
            #pragma unroll
            for (int j = 0; j < 4; j++) b[j] = Es[k][tx * 4 + j];
            #pragma unroll
            for (int i = 0; i < 4; i++)
                #pragma unroll
                for (int j = 0; j < 4; j++) acc[i][j] += a[i] * b[j];
        }
        __syncthreads();
    }
    #pragma unroll
    for (int i = 0; i < 4; i++) {
        int d = dBase + ty * 4 + i;
        float g = gamma[d];
        #pragma unroll
        for (int j = 0; j < 4; j++)
            g_Ap[(size_t)d * Rk + sBase + tx * 4 + j] = g * acc[i][j];
    }
}

// per-row LN stats + feat
__global__ void kStats(const float* __restrict__ x, const float* __restrict__ gamma) {
    __shared__ float sm[256];
    int row = blockIdx.x;
    int t = threadIdx.x;
    const float* xr = x + (size_t)row * Dk;
    float s = 0.f, s2 = 0.f, sg = 0.f;
    for (int j = t; j < Dk; j += 256) {
        float v = xr[j];
        s += v; s2 += v * v; sg += gamma[j] * v;
    }
    float S  = blockReduce256(s, sm);
    float S2 = blockReduce256(s2, sm);
    float SG = blockReduce256(sg, sm);
    if (t == 0) {
        float mean = S / Dk;
        float var = S2 / Dk - mean * mean;
        float rstd = rsqrtf(var + 1e-5f);
        g_rstd[row] = rstd;
        g_nmr[row]  = -mean * rstd;
        g_feat[row] = (SG - mean * g_consts[0]) * rstd / Dk + g_consts[1] / Dk;
    }
}

// scale[l] and fused gate: G[l] = sigmoid(g_logit[...]) * scale[l]
__global__ void kScale(const float* __restrict__ phib, const float* __restrict__ glog,
                       const int* __restrict__ step_p, int glen) {
    __shared__ float sm[256];
    const float PI_F = 3.14159274101257324f;  // float32(pi), matches jnp weak-type cast
    int l = blockIdx.x;
    int t = threadIdx.x;  // r index, Rk == 256
    // exact reference fp32 ordering: ((pi * (t+0.5)) * k) / L
    float ang = ((PI_F * ((float)l + 0.5f)) * (float)t) / (float)Lk;
    float c1 = cosf(ang);
    float c2 = phib[(size_t)l * Rk + t];
    float c3 = (t < Bk) ? g_feat[(size_t)t * Lk + l] : 0.f;
    float S1 = blockReduce256(c1, sm);
    float S2 = blockReduce256(c2, sm);
    float S3 = blockReduce256(c3, sm);
    if (t == 0) {
        int step = *step_p;
        float det_scale = fminf((float)((double)step / 2000.0), 1.0f);
        float sdet = S1 / (float)Rk;
        float pbm  = S2 / (float)Rk;
        float fbar = S3 / (float)Bk;
        float wbar = g_consts[2] / (float)Rk;
        float scale = det_scale * sdet + pbm + fbar * wbar;
        int gi = l / (Dk / glen);
        float gs = 1.0f / (1.0f + expf(-glog[gi]));
        g_G[l] = gs * scale;
    }
}

// ---------------- GEMM 1: U = (X @ A')*rstd + nmr*cA + cB ----------------
// M=16384, K=2048, N=256.  128x128 tiles, BK=8, 256 threads, 8x8 per thread.
__global__ __launch_bounds__(256) void kGemm1(const float* __restrict__ X) {
    __shared__ float As[8][128];
    __shared__ float Bs[8][128];
    int t = threadIdx.x;
    int rowBase = blockIdx.y * 128, colBase = blockIdx.x * 128;
    int lm = t >> 1, lkq = (t & 1) * 4;
    int lk = t >> 5, lnq = (t & 31) * 4;
    const float* Aptr = X + (size_t)(rowBase + lm) * Dk + lkq;
    const float* Bptr = g_Ap + (size_t)lk * Rk + colBase + lnq;
    int ty = t >> 4, tx = t & 15;
    float acc[8][8] = {};
    for (int k0 = 0; k0 < Dk; k0 += 8) {
        float4 av = *(const float4*)(Aptr + k0);
        float4 bv = *(const float4*)(Bptr + (size_t)k0 * Rk);
        As[lkq + 0][lm] = av.x; As[lkq + 1][lm] = av.y;
        As[lkq + 2][lm] = av.z; As[lkq + 3][lm] = av.w;
        *(float4*)&Bs[lk][lnq] = bv;
        __syncthreads();
        #pragma unroll
        for (int k = 0; k < 8; k++) {
            float a[8], b[8];
            *(float4*)(a)     = *(float4*)&As[k][ty * 8];
            *(float4*)(a + 4) = *(float4*)&As[k][ty * 8 + 4];
            *(float4*)(b)     = *(float4*)&Bs[k][tx * 8];
            *(float4*)(b + 4) = *(float4*)&Bs[k][tx * 8 + 4];
            #pragma unroll
            for (int i = 0; i < 8; i++)
                #pragma unroll
                for (int j = 0; j < 8; j++) acc[i][j] += a[i] * b[j];
        }
        __syncthreads();
    }
    float rs[8], nm[8], ca[8], cb[8];
    #pragma unroll
    for (int i = 0; i < 8; i++) {
        int row = rowBase + ty * 8 + i;
        rs[i] = g_rstd[row]; nm[i] = g_nmr[row];
    }
    #pragma unroll
    for (int j = 0; j < 8; j++) {
        int col = colBase + tx * 8 + j;
        ca[j] = g_cA[col]; cb[j] = g_cB[col];
    }
    #pragma unroll
    for (int i = 0; i < 8; i++) {
        int row = rowBase + ty * 8 + i;
        #pragma unroll
        for (int j = 0; j < 8; j++) {
            int col = colBase + tx * 8 + j;
            g_U[(size_t)row * Rk + col] = acc[i][j] * rs[i] + nm[i] * ca[j] + cb[j];
        }
    }
}

// ---------------- GEMM 2: out = G[d] * (U @ Wq + bq) ----------------
// M=16384, K=256, N=2048.
__global__ __launch_bounds__(256) void kGemm2(const float* __restrict__ Wq,
                                              const float* __restrict__ bq,
                                              float* __restrict__ out) {
    __shared__ float As[8][128];
    __shared__ float Bs[8][128];
    int t = threadIdx.x;
    int rowBase = blockIdx.y * 128, colBase = blockIdx.x * 128;
    int lm = t >> 1, lkq = (t & 1) * 4;
    int lk = t >> 5, lnq = (t & 31) * 4;
    const float* Aptr = g_U + (size_t)(rowBase + lm) * Rk + lkq;
    const float* Bptr = Wq + (size_t)lk * Dk + colBase + lnq;
    int ty = t >> 4, tx = t & 15;
    float acc[8][8] = {};
    for (int k0 = 0; k0 < Rk; k0 += 8) {
        float4 av = *(const float4*)(Aptr + k0);
        float4 bv = *(const float4*)(Bptr + (size_t)k0 * Dk);
        As[lkq + 0][lm] = av.x; As[lkq + 1][lm] = av.y;
        As[lkq + 2][lm] = av.z; As[lkq + 3][lm] = av.w;
        *(float4*)&Bs[lk][lnq] = bv;
        __syncthreads();
        #pragma unroll
        for (int k = 0; k < 8; k++) {
            float a[8], b[8];
            *(float4*)(a)     = *(float4*)&As[k][ty * 8];
            *(float4*)(a + 4) = *(float4*)&As[k][ty * 8 + 4];
            *(float4*)(b)     = *(float4*)&Bs[k][tx * 8];
            *(float4*)(b + 4) = *(float4*)&Bs[k][tx * 8 + 4];
            #pragma unroll
            for (int i = 0; i < 8; i++)
                #pragma unroll
                for (int j = 0; j < 8; j++) acc[i][j] += a[i] * b[j];
        }
        __syncthreads();
    }
    float gv[8], bv2[8];
    #pragma unroll
    for (int j = 0; j < 8; j++) {
        int col = colBase + tx * 8 + j;
        gv[j] = g_G[col]; bv2[j] = bq[col];
    }
    #pragma unroll
    for (int i = 0; i < 8; i++) {
        int row = rowBase + ty * 8 + i;
        #pragma unroll
        for (int j = 0; j < 8; j++) {
            int col = colBase + tx * 8 + j;
            out[(size_t)row * Dk + col] = gv[j] * (acc[i][j] + bv2[j]);
        }
    }
}

// ---------------- launch ----------------
extern "C" void kernel_launch(void* const* d_in, const int* in_sizes, int n_in,
                              void* d_out, int out_size) {
    const float* x     = (const float*)d_in[0];
    const float* gamma = (const float*)d_in[1];
    const float* beta  = (const float*)d_in[2];
    const float* P     = (const float*)d_in[3];
    const float* dlt   = (const float*)d_in[4];
    const float* phiw  = (const float*)d_in[5];
    const float* phib  = (const float*)d_in[6];
    const float* toep  = (const float*)d_in[7];
    const float* Wq    = (const float*)d_in[8];
    const float* bq    = (const float*)d_in[9];
    const float* glog  = (const float*)d_in[10];
    const int*   step  = (const int*)d_in[11];
    int Kc   = in_sizes[7];
    int glen = in_sizes[10];

    kConst<<<1, 256>>>(gamma, beta, phiw);
    kPgb1<<<32, 256>>>(P, gamma, beta);
    kPgb2<<<1, 256>>>();
    kE<<<Rk, 256>>>(dlt, toep, Kc);
    kAp<<<dim3(Rk / 64, Dk / 64), 256>>>(P, gamma);
    kStats<<<BLk, 256>>>(x, gamma);
    kScale<<<Lk, 256>>>(phib, glog, step, glen);
    kGemm1<<<dim3(Rk / 128, BLk / 128), 256>>>(x);
    kGemm2<<<dim3(Dk / 128, BLk / 128), 256>>>(Wq, bq, (float*)d_out);
}

// round 3
// speedup vs baseline: 3.1123x; 3.1123x over previous
#include <cuda_runtime.h>
#include <cstdint>
#include <math.h>

#define Bk 8
#define Lk 2048
#define Dk 2048
#define Rk 256
#define BLk (Bk * Lk)   // 16384 rows

// ---------------- device scratch ----------------
static __device__ float g_E[Rk * Rk];               // E = T @ dlt_T       (256x256)
static __device__ uint32_t g_BT1[Rk * Dk];          // A'^T tf32 bits      (256x2048)
static __device__ uint32_t g_WqT[Dk * Rk];          // Wq^T tf32 bits      (2048x256)
static __device__ uint32_t g_U[(size_t)BLk * Rk];   // z_mixed tf32 bits
static __device__ float g_feat[BLk];
static __device__ float g_pg[Rk], g_pb[Rk];
static __device__ float g_cA[Rk], g_cB[Rk];
static __device__ float g_G[Dk];                    // sigmoid(g)[d] * scale[d]
static __device__ float g_consts[4];
static __device__ float g_pgp[32 * Rk], g_pbp[32 * Rk];

// ---------------- helpers ----------------
__device__ __forceinline__ uint32_t smem_u32(const void* p) {
    uint32_t a;
    asm("{ .reg .u64 t; cvta.to.shared.u64 t, %1; cvt.u32.u64 %0, t; }" : "=r"(a) : "l"(p));
    return a;
}
__device__ __forceinline__ uint32_t tf32r(float x) {
    uint32_t u;
    asm("cvt.rna.tf32.f32 %0, %1;" : "=r"(u) : "f"(x));
    return u;
}
__device__ __forceinline__ uint4 tf32x4(float4 v) {
    uint4 u;
    u.x = tf32r(v.x); u.y = tf32r(v.y); u.z = tf32r(v.z); u.w = tf32r(v.w);
    return u;
}
__device__ __forceinline__ void cp16(void* dst, const void* src) {
    uint32_t d = smem_u32(dst);
    asm volatile("cp.async.cg.shared.global [%0], [%1], 16;" :: "r"(d), "l"(src) : "memory");
}
#define CP_COMMIT() asm volatile("cp.async.commit_group;" ::: "memory")
#define CP_WAIT0()  asm volatile("cp.async.wait_group 0;" ::: "memory")

#define MMA_TF32(c, a, b) \
    asm volatile( \
        "mma.sync.aligned.m16n8k8.row.col.f32.tf32.tf32.f32 " \
        "{%0,%1,%2,%3},{%4,%5,%6,%7},{%8,%9},{%0,%1,%2,%3};" \
        : "+f"((c)[0]), "+f"((c)[1]), "+f"((c)[2]), "+f"((c)[3]) \
        : "r"((a)[0]), "r"((a)[1]), "r"((a)[2]), "r"((a)[3]), \
          "r"((b)[0]), "r"((b)[1]))

__device__ __forceinline__ float blockReduce256(float v, float* sm) {
    int t = threadIdx.x;
    sm[t] = v;
    __syncthreads();
    #pragma unroll
    for (int off = 128; off > 0; off >>= 1) {
        if (t < off) sm[t] += sm[t + off];
        __syncthreads();
    }
    float r = sm[0];
    __syncthreads();
    return r;
}

// ---------------- precompute kernels ----------------
__global__ void kConst(const float* __restrict__ gamma, const float* __restrict__ beta,
                       const float* __restrict__ phiw) {
    __shared__ float sm[256];
    int t = threadIdx.x;
    float a = 0.f, b = 0.f, c = 0.f;
    for (int j = t; j < Dk; j += 256) { a += gamma[j]; b += beta[j]; }
    for (int j = t; j < Rk; j += 256) { c += phiw[j]; }
    float A = blockReduce256(a, sm);
    float B = blockReduce256(b, sm);
    float C = blockReduce256(c, sm);
    if (t == 0) { g_consts[0] = A; g_consts[1] = B; g_consts[2] = C; }
}

__global__ void kPgb1(const float* __restrict__ P, const float* __restrict__ gamma,
                      const float* __restrict__ beta) {
    int r = threadIdx.x;
    int chunk = blockIdx.x;
    float ag = 0.f, ab = 0.f;
    #pragma unroll 4
    for (int j = 0; j < 64; j++) {
        int d = chunk * 64 + j;
        float p = P[(size_t)d * Rk + r];
        ag += gamma[d] * p;
        ab += beta[d] * p;
    }
    g_pgp[chunk * Rk + r] = ag;
    g_pbp[chunk * Rk + r] = ab;
}
__global__ void kPgb2() {
    int r = threadIdx.x;
    float a = 0.f, b = 0.f;
    #pragma unroll
    for (int c = 0; c < 32; c++) { a += g_pgp[c * Rk + r]; b += g_pbp[c * Rk + r]; }
    g_pg[r] = a;
    g_pb[r] = b;
}

// E[s,r] = sum_i toep[i-s+pad]*dlt[i,r]; 4 s per block
__global__ void kE(const float* __restrict__ dlt, const float* __restrict__ toep, int Kc) {
    __shared__ float st[256];
    int r = threadIdx.x;
    int s0 = blockIdx.x * 4;
    if (r < Kc) st[r] = toep[r];
    __syncthreads();
    int pad = (Kc - 1) >> 1;
    float a0 = 0.f, a1 = 0.f, a2 = 0.f, a3 = 0.f;
    for (int i = 0; i < Rk; i++) {
        float v = dlt[(size_t)i * Rk + r];
        int base = i - s0 + pad;
        if ((unsigned)base       < (unsigned)Kc) a0 += st[base] * v;
        if ((unsigned)(base - 1) < (unsigned)Kc) a1 += st[base - 1] * v;
        if ((unsigned)(base - 2) < (unsigned)Kc) a2 += st[base - 2] * v;
        if ((unsigned)(base - 3) < (unsigned)Kc) a3 += st[base - 3] * v;
    }
    g_E[(size_t)(s0 + 0) * Rk + r] = a0;
    g_E[(size_t)(s0 + 1) * Rk + r] = a1;
    g_E[(size_t)(s0 + 2) * Rk + r] = a2;
    g_E[(size_t)(s0 + 3) * Rk + r] = a3;
}

__global__ void kCab() {
    __shared__ float sm[256];
    int s = blockIdx.x, r = threadIdx.x;
    float e = g_E[(size_t)s * Rk + r];
    float ca = blockReduce256(g_pg[r] * e, sm);
    float cb = blockReduce256(g_pb[r] * e, sm);
    if (r == 0) { g_cA[s] = ca; g_cB[s] = cb; }
}

// A'^T[s,d] = gamma[d] * sum_r P[d,r] E[s,r] -> g_BT1 (tf32)
__global__ __launch_bounds__(256) void kAp(const float* __restrict__ P,
                                           const float* __restrict__ gamma) {
    __shared__ float Ps[16][64];
    __shared__ float Es[16][64];
    int dBase = blockIdx.y * 64, sBase = blockIdx.x * 64;
    int t = threadIdx.x;
    int ty = t >> 4, tx = t & 15;
    float acc[4][4] = {};
    for (int k0 = 0; k0 < Rk; k0 += 16) {
        {
            int m = t >> 2, kq = (t & 3) * 4;
            float4 v = *(const float4*)&P[(size_t)(dBase + m) * Rk + k0 + kq];
            Ps[kq + 0][m] = v.x; Ps[kq + 1][m] = v.y; Ps[kq + 2][m] = v.z; Ps[kq + 3][m] = v.w;
        }
        {
            int n = t >> 2, kq = (t & 3) * 4;
            float4 v = *(const float4*)&g_E[(size_t)(sBase + n) * Rk + k0 + kq];
            Es[kq + 0][n] = v.x; Es[kq + 1][n] = v.y; Es[kq + 2][n] = v.z; Es[kq + 3][n] = v.w;
        }
        __syncthreads();
        #pragma unroll
        for (int k = 0; k < 16; k++) {
            float a[4], b[4];
            #pragma unroll
            for (int i = 0; i < 4; i++) a[i] = Ps[k][ty * 4 + i];
            #pragma unroll
            for (int j = 0; j < 4; j++) b[j] = Es[k][tx * 4 + j];
            #pragma unroll
            for (int i = 0; i < 4; i++)
                #pragma unroll
                for (int j = 0; j < 4; j++) acc[i][j] += a[i] * b[j];
        }
        __syncthreads();
    }
    #pragma unroll
    for (int i = 0; i < 4; i++) {
        int d = dBase + ty * 4 + i;
        float g = gamma[d];
        #pragma unroll
        for (int j = 0; j < 4; j++) {
            int s = sBase + tx * 4 + j;
            g_BT1[(size_t)s * Dk + d] = tf32r(g * acc[i][j]);
        }
    }
}

// WqT[d,r] = tf32(Wq[r,d])
__global__ void kWqT(const float* __restrict__ Wq) {
    __shared__ float tile[32][33];
    int bx = blockIdx.x, by = blockIdx.y;
    int tx = threadIdx.x & 31, ty8 = threadIdx.x >> 5;
    #pragma unroll
    for (int i = 0; i < 32; i += 8)
        tile[ty8 + i][tx] = Wq[(size_t)(by * 32 + ty8 + i) * Dk + bx * 32 + tx];
    __syncthreads();
    #pragma unroll
    for (int i = 0; i < 32; i += 8)
        g_WqT[(size_t)(bx * 32 + ty8 + i) * Rk + by * 32 + tx] = tf32r(tile[tx][ty8 + i]);
}

// G[l] = sigmoid(g_logit[..]) * scale[l]
__global__ void kScale(const float* __restrict__ phib, const float* __restrict__ glog,
                       const int* __restrict__ step_p, int glen) {
    int w = threadIdx.x >> 5, lane = threadIdx.x & 31;
    int l = blockIdx.x * 8 + w;
    const float PI_F = 3.14159274101257324f;
    float base = PI_F * ((float)l + 0.5f);
    float c1 = 0.f, c2 = 0.f;
    #pragma unroll
    for (int j = 0; j < 8; j++) {
        int r = lane + 32 * j;
        c1 += cosf((base * (float)r) / (float)Lk);
        c2 += phib[(size_t)l * Rk + r];
    }
    float c3 = (lane < Bk) ? g_feat[(size_t)lane * Lk + l] : 0.f;
    #pragma unroll
    for (int o = 16; o > 0; o >>= 1) {
        c1 += __shfl_xor_sync(0xffffffffu, c1, o);
        c2 += __shfl_xor_sync(0xffffffffu, c2, o);
        c3 += __shfl_xor_sync(0xffffffffu, c3, o);
    }
    if (lane == 0) {
        int step = *step_p;
        float det_scale = fminf((float)((double)step / 2000.0), 1.0f);
        float scale = det_scale * (c1 / (float)Rk) + (c2 / (float)Rk)
                    + (c3 / (float)Bk) * (g_consts[2] / (float)Rk);
        int gi = l / (Dk / glen);
        float gs = 1.0f / (1.0f + expf(-glog[gi]));
        g_G[l] = gs * scale;
    }
}

// ================= mma.sync GEMM 1 =================
// U = (X @ A')*rstd + nmr*cA + cB ; M=16384, N=256, K=2048. Fused LN stats.
// grid (2, 128), 256 threads, CTA tile 128x128, BK=16.
#define NT1 (Dk / 16)

__global__ __launch_bounds__(256) void kGemm1MMA(const float* __restrict__ X,
                                                 const float* __restrict__ gamma) {
    __shared__ uint32_t As[2][128 * 16];
    __shared__ uint32_t Bs[2][128 * 16];
    __shared__ float s_rstd[128], s_nmr[128];

    int t = threadIdx.x;
    int w = t >> 5, lane = t & 31, g = lane >> 2, tg = lane & 3;
    int rowBase = blockIdx.y * 128, colBase = blockIdx.x * 128;
    int m0w = (w >> 2) * 64, n0w = (w & 3) * 32;

    int lr = t >> 2, lq = t & 3;                       // staging row / k-quad
    int sq = 4 * (lq ^ ((lr >> 1) & 3));               // swizzled k-offset for stores
    int swf = ((g >> 1) & 3) << 2;                     // fragment swizzle

    const float4* Xr0 = (const float4*)(X + (size_t)(rowBase + lr) * Dk);
    const float4* Xr1 = (const float4*)(X + (size_t)(rowBase + lr + 64) * Dk);
    const float4* Br0 = (const float4*)(g_BT1 + (size_t)(colBase + lr) * Dk);
    const float4* Br1 = (const float4*)(g_BT1 + (size_t)(colBase + lr + 64) * Dk);
    const float4* Gm  = (const float4*)gamma;

    float acc[4][4][4] = {};
    float s0 = 0.f, s20 = 0.f, sg0 = 0.f, s1 = 0.f, s21 = 0.f, sg1 = 0.f;

    // prologue: tile 0
    cp16(&Bs[0][lr * 16 + sq], Br0 + lq);
    cp16(&Bs[0][(lr + 64) * 16 + sq], Br1 + lq);
    CP_COMMIT();
    {
        float4 x0 = Xr0[lq], x1 = Xr1[lq], gv = Gm[lq];
        s0 += (x0.x + x0.y) + (x0.z + x0.w);
        s20 += x0.x * x0.x + x0.y * x0.y + x0.z * x0.z + x0.w * x0.w;
        sg0 += gv.x * x0.x + gv.y * x0.y + gv.z * x0.z + gv.w * x0.w;
        s1 += (x1.x + x1.y) + (x1.z + x1.w);
        s21 += x1.x * x1.x + x1.y * x1.y + x1.z * x1.z + x1.w * x1.w;
        sg1 += gv.x * x1.x + gv.y * x1.y + gv.z * x1.z + gv.w * x1.w;
        *(uint4*)&As[0][lr * 16 + sq] = tf32x4(x0);
        *(uint4*)&As[0][(lr + 64) * 16 + sq] = tf32x4(x1);
    }
    CP_WAIT0();
    __syncthreads();

    #pragma unroll 1
    for (int tt = 0; tt < NT1; ++tt) {
        int buf = tt & 1, nbuf = buf ^ 1;
        float4 x0, x1, gv;
        if (tt + 1 < NT1) {
            int src = (tt + 1) * 4 + lq;
            cp16(&Bs[nbuf][lr * 16 + sq], Br0 + src);
            cp16(&Bs[nbuf][(lr + 64) * 16 + sq], Br1 + src);
            CP_COMMIT();
            x0 = Xr0[src]; x1 = Xr1[src]; gv = Gm[src];
        }
        // compute tile tt
        #pragma unroll
        for (int ks = 0; ks < 2; ++ks) {
            int klo = (ks * 8 + tg) ^ swf;
            int khi = klo ^ 4;
            uint32_t af[4][4], bf[4][2];
            #pragma unroll
            for (int mi = 0; mi < 4; ++mi) {
                const uint32_t* ap = &As[buf][(m0w + mi * 16 + g) * 16];
                af[mi][0] = ap[klo]; af[mi][1] = ap[128 + klo];
                af[mi][2] = ap[khi]; af[mi][3] = ap[128 + khi];
            }
            #pragma unroll
            for (int ni = 0; ni < 4; ++ni) {
                const uint32_t* bp = &Bs[buf][(n0w + ni * 8 + g) * 16];
                bf[ni][0] = bp[klo]; bf[ni][1] = bp[khi];
            }
            #pragma unroll
            for (int mi = 0; mi < 4; ++mi)
                #pragma unroll
                for (int ni = 0; ni < 4; ++ni)
                    MMA_TF32(acc[mi][ni], af[mi], bf[ni]);
        }
        if (tt + 1 < NT1) {
            s0 += (x0.x + x0.y) + (x0.z + x0.w);
            s20 += x0.x * x0.x + x0.y * x0.y + x0.z * x0.z + x0.w * x0.w;
            sg0 += gv.x * x0.x + gv.y * x0.y + gv.z * x0.z + gv.w * x0.w;
            s1 += (x1.x + x1.y) + (x1.z + x1.w);
            s21 += x1.x * x1.x + x1.y * x1.y + x1.z * x1.z + x1.w * x1.w;
            sg1 += gv.x * x1.x + gv.y * x1.y + gv.z * x1.z + gv.w * x1.w;
            *(uint4*)&As[nbuf][lr * 16 + sq] = tf32x4(x0);
            *(uint4*)&As[nbuf][(lr + 64) * 16 + sq] = tf32x4(x1);
        }
        CP_WAIT0();
        __syncthreads();
    }

    // LN stats reduce (4 staging threads per row)
    #pragma unroll
    for (int o = 1; o <= 2; o <<= 1) {
        s0  += __shfl_xor_sync(0xffffffffu, s0, o);
        s20 += __shfl_xor_sync(0xffffffffu, s20, o);
        sg0 += __shfl_xor_sync(0xffffffffu, sg0, o);
        s1  += __shfl_xor_sync(0xffffffffu, s1, o);
        s21 += __shfl_xor_sync(0xffffffffu, s21, o);
        sg1 += __shfl_xor_sync(0xffffffffu, sg1, o);
    }
    if (lq == 0) {
        float C0 = g_consts[0], C1 = g_consts[1];
        float mean = s0 * (1.f / Dk);
        float var = s20 * (1.f / Dk) - mean * mean;
        float rstd = rsqrtf(var + 1e-5f);
        s_rstd[lr] = rstd; s_nmr[lr] = -mean * rstd;
        if (blockIdx.x == 0)
            g_feat[rowBase + lr] = (sg0 - mean * C0) * rstd * (1.f / Dk) + C1 * (1.f / Dk);
        mean = s1 * (1.f / Dk);
        var = s21 * (1.f / Dk) - mean * mean;
        rstd = rsqrtf(var + 1e-5f);
        s_rstd[lr + 64] = rstd; s_nmr[lr + 64] = -mean * rstd;
        if (blockIdx.x == 0)
            g_feat[rowBase + lr + 64] = (sg1 - mean * C0) * rstd * (1.f / Dk) + C1 * (1.f / Dk);
    }
    __syncthreads();

    // epilogue -> g_U (tf32 bits)
    #pragma unroll
    for (int ni = 0; ni < 4; ++ni) {
        int cg = colBase + n0w + ni * 8 + 2 * tg;
        float ca0 = g_cA[cg], ca1 = g_cA[cg + 1];
        float cb0 = g_cB[cg], cb1 = g_cB[cg + 1];
        #pragma unroll
        for (int mi = 0; mi < 4; ++mi) {
            int r1 = m0w + mi * 16 + g;
            float rs1 = s_rstd[r1], nm1 = s_nmr[r1];
            float rs2 = s_rstd[r1 + 8], nm2 = s_nmr[r1 + 8];
            uint2 o1, o2;
            o1.x = tf32r(acc[mi][ni][0] * rs1 + nm1 * ca0 + cb0);
            o1.y = tf32r(acc[mi][ni][1] * rs1 + nm1 * ca1 + cb1);
            o2.x = tf32r(acc[mi][ni][2] * rs2 + nm2 * ca0 + cb0);
            o2.y = tf32r(acc[mi][ni][3] * rs2 + nm2 * ca1 + cb1);
            *(uint2*)&g_U[(size_t)(rowBase + r1) * Rk + cg] = o1;
            *(uint2*)&g_U[(size_t)(rowBase + r1 + 8) * Rk + cg] = o2;
        }
    }
}

// ================= mma.sync GEMM 2 =================
// out = G[d]*(U @ Wq + bq) ; M=16384, N=2048, K=256. grid (16, 128).
#define NT2 (Rk / 16)

__global__ __launch_bounds__(256) void kGemm2MMA(const float* __restrict__ bq,
                                                 float* __restrict__ out) {
    __shared__ uint32_t As[2][128 * 16];
    __shared__ uint32_t Bs[2][128 * 16];

    int t = threadIdx.x;
    int w = t >> 5, lane = t & 31, g = lane >> 2, tg = lane & 3;
    int rowBase = blockIdx.y * 128, colBase = blockIdx.x * 128;
    int m0w = (w >> 2) * 64, n0w = (w & 3) * 32;

    int lr = t >> 2, lq = t & 3;
    int sq = 4 * (lq ^ ((lr >> 1) & 3));
    int swf = ((g >> 1) & 3) << 2;

    const float4* Ar0 = (const float4*)(g_U + (size_t)(rowBase + lr) * Rk);
    const float4* Ar1 = (const float4*)(g_U + (size_t)(rowBase + lr + 64) * Rk);
    const float4* Br0 = (const float4*)(g_WqT + (size_t)(colBase + lr) * Rk);
    const float4* Br1 = (const float4*)(g_WqT + (size_t)(colBase + lr + 64) * Rk);

    float acc[4][4][4] = {};

    cp16(&As[0][lr * 16 + sq], Ar0 + lq);
    cp16(&As[0][(lr + 64) * 16 + sq], Ar1 + lq);
    cp16(&Bs[0][lr * 16 + sq], Br0 + lq);
    cp16(&Bs[0][(lr + 64) * 16 + sq], Br1 + lq);
    CP_COMMIT();
    CP_WAIT0();
    __syncthreads();

    #pragma unroll 1
    for (int tt = 0; tt < NT2; ++tt) {
        int buf = tt & 1, nbuf = buf ^ 1;
        if (tt + 1 < NT2) {
            int src = (tt + 1) * 4 + lq;
            cp16(&As[nbuf][lr * 16 + sq], Ar0 + src);
            cp16(&As[nbuf][(lr + 64) * 16 + sq], Ar1 + src);
            cp16(&Bs[nbuf][lr * 16 + sq], Br0 + src);
            cp16(&Bs[nbuf][(lr + 64) * 16 + sq], Br1 + src);
            CP_COMMIT();
        }
        #pragma unroll
        for (int ks = 0; ks < 2; ++ks) {
            int klo = (ks * 8 + tg) ^ swf;
            int khi = klo ^ 4;
            uint32_t af[4][4], bf[4][2];
            #pragma unroll
            for (int mi = 0; mi < 4; ++mi) {
                const uint32_t* ap = &As[buf][(m0w + mi * 16 + g) * 16];
                af[mi][0] = ap[klo]; af[mi][1] = ap[128 + klo];
                af[mi][2] = ap[khi]; af[mi][3] = ap[128 + khi];
            }
            #pragma unroll
            for (int ni = 0; ni < 4; ++ni) {
                const uint32_t* bp = &Bs[buf][(n0w + ni * 8 + g) * 16];
                bf[ni][0] = bp[klo]; bf[ni][1] = bp[khi];
            }
            #pragma unroll
            for (int mi = 0; mi < 4; ++mi)
                #pragma unroll
                for (int ni = 0; ni < 4; ++ni)
                    MMA_TF32(acc[mi][ni], af[mi], bf[ni]);
        }
        CP_WAIT0();
        __syncthreads();
    }

    #pragma unroll
    for (int ni = 0; ni < 4; ++ni) {
        int cg = colBase + n0w + ni * 8 + 2 * tg;
        float G0 = g_G[cg], G1 = g_G[cg + 1];
        float q0 = bq[cg], q1 = bq[cg + 1];
        #pragma unroll
        for (int mi = 0; mi < 4; ++mi) {
            int r1 = rowBase + m0w + mi * 16 + g;
            float2 o1, o2;
            o1.x = G0 * (acc[mi][ni][0] + q0);
            o1.y = G1 * (acc[mi][ni][1] + q1);
            o2.x = G0 * (acc[mi][ni][2] + q0);
            o2.y = G1 * (acc[mi][ni][3] + q1);
            *(float2*)&out[(size_t)r1 * Dk + cg] = o1;
            *(float2*)&out[(size_t)(r1 + 8) * Dk + cg] = o2;
        }
    }
}

// ---------------- launch ----------------
extern "C" void kernel_launch(void* const* d_in, const int* in_sizes, int n_in,
                              void* d_out, int out_size) {
    const float* x     = (const float*)d_in[0];
    const float* gamma = (const float*)d_in[1];
    const float* beta  = (const float*)d_in[2];
    const float* P     = (const float*)d_in[3];
    const float* dlt   = (const float*)d_in[4];
    const float* phiw  = (const float*)d_in[5];
    const float* phib  = (const float*)d_in[6];
    const float* toep  = (const float*)d_in[7];
    const float* Wq    = (const float*)d_in[8];
    const float* bq    = (const float*)d_in[9];
    const float* glog  = (const float*)d_in[10];
    const int*   step  = (const int*)d_in[11];
    int Kc   = in_sizes[7];
    int glen = in_sizes[10];

    kConst<<<1, 256>>>(gamma, beta, phiw);
    kPgb1<<<32, 256>>>(P, gamma, beta);
    kPgb2<<<1, 256>>>();
    kE<<<64, 256>>>(dlt, toep, Kc);
    kCab<<<Rk, 256>>>();
    kAp<<<dim3(Rk / 64, Dk / 64), 256>>>(P, gamma);
    kWqT<<<dim3(Dk / 32, Rk / 32), 256>>>(Wq);
    kGemm1MMA<<<dim3(2, 128), 256>>>(x, gamma);
    kScale<<<Lk / 8, 256>>>(phib, glog, step, glen);
    kGemm2MMA<<<dim3(16, 128), 256>>>(bq, (float*)d_out);
}

// round 4
// speedup vs baseline: 3.7499x; 1.2049x over previous
#include <cuda_runtime.h>
#include <cuda_fp16.h>
#include <cstdint>
#include <math.h>

#define Bk 8
#define Lk 2048
#define Dk 2048
#define Rk 256
#define BLk (Bk * Lk)   // 16384 rows

// ---------------- device scratch ----------------
static __device__ float g_E[Rk * Rk];                 // E = T @ dlt_T     (256x256)
static __device__ __half g_BT1[Rk * Dk];              // A'^T fp16         (256x2048)
static __device__ __half g_WqT[Dk * Rk];              // Wq^T fp16         (2048x256)
static __device__ __half g_U[(size_t)BLk * Rk];       // z_mixed fp16
static __device__ float g_feat[BLk];
static __device__ float g_pg[Rk], g_pb[Rk];
static __device__ float g_cA[Rk], g_cB[Rk];
static __device__ float g_G[Dk];
static __device__ float g_consts[4];
static __device__ float g_pgp[32 * Rk], g_pbp[32 * Rk];

// ---------------- helpers ----------------
__device__ __forceinline__ uint32_t smem_u32(const void* p) {
    uint32_t a;
    asm("{ .reg .u64 t; cvta.to.shared.u64 t, %1; cvt.u32.u64 %0, t; }" : "=r"(a) : "l"(p));
    return a;
}
__device__ __forceinline__ void cp16(void* dst, const void* src) {
    uint32_t d = smem_u32(dst);
    asm volatile("cp.async.cg.shared.global [%0], [%1], 16;" :: "r"(d), "l"(src) : "memory");
}
#define CP_COMMIT() asm volatile("cp.async.commit_group;" ::: "memory")
#define CP_WAIT0()  asm volatile("cp.async.wait_group 0;" ::: "memory")

#define LDSM4(r0, r1, r2, r3, addr) \
    asm volatile("ldmatrix.sync.aligned.m8n8.x4.shared.b16 {%0,%1,%2,%3}, [%4];" \
        : "=r"(r0), "=r"(r1), "=r"(r2), "=r"(r3) : "r"(addr))

#define MMAF16(c, a, b) \
    asm volatile( \
        "mma.sync.aligned.m16n8k16.row.col.f32.f16.f16.f32 " \
        "{%0,%1,%2,%3},{%4,%5,%6,%7},{%8,%9},{%0,%1,%2,%3};" \
        : "+f"((c)[0]), "+f"((c)[1]), "+f"((c)[2]), "+f"((c)[3]) \
        : "r"((a)[0]), "r"((a)[1]), "r"((a)[2]), "r"((a)[3]), \
          "r"((b)[0]), "r"((b)[1]))

__device__ __forceinline__ uint32_t h2pack(float a, float b) {
    __half2 h = __floats2half2_rn(a, b);
    return *reinterpret_cast<uint32_t*>(&h);
}

__device__ __forceinline__ float blockReduce256(float v, float* sm) {
    int t = threadIdx.x;
    sm[t] = v;
    __syncthreads();
    #pragma unroll
    for (int off = 128; off > 0; off >>= 1) {
        if (t < off) sm[t] += sm[t + off];
        __syncthreads();
    }
    float r = sm[0];
    __syncthreads();
    return r;
}

// ---------------- precompute kernels ----------------
__global__ void kConst(const float* __restrict__ gamma, const float* __restrict__ beta,
                       const float* __restrict__ phiw) {
    __shared__ float sm[256];
    int t = threadIdx.x;
    float a = 0.f, b = 0.f, c = 0.f;
    for (int j = t; j < Dk; j += 256) { a += gamma[j]; b += beta[j]; }
    for (int j = t; j < Rk; j += 256) { c += phiw[j]; }
    float A = blockReduce256(a, sm);
    float B = blockReduce256(b, sm);
    float C = blockReduce256(c, sm);
    if (t == 0) { g_consts[0] = A; g_consts[1] = B; g_consts[2] = C; }
}

__global__ void kPgb1(const float* __restrict__ P, const float* __restrict__ gamma,
                      const float* __restrict__ beta) {
    int r = threadIdx.x;
    int chunk = blockIdx.x;
    float ag = 0.f, ab = 0.f;
    #pragma unroll 4
    for (int j = 0; j < 64; j++) {
        int d = chunk * 64 + j;
        float p = P[(size_t)d * Rk + r];
        ag += gamma[d] * p;
        ab += beta[d] * p;
    }
    g_pgp[chunk * Rk + r] = ag;
    g_pbp[chunk * Rk + r] = ab;
}
__global__ void kPgb2() {
    int r = threadIdx.x;
    float a = 0.f, b = 0.f;
    #pragma unroll
    for (int c = 0; c < 32; c++) { a += g_pgp[c * Rk + r]; b += g_pbp[c * Rk + r]; }
    g_pg[r] = a;
    g_pb[r] = b;
}

// E[s,r] = sum_i toep[i-s+pad]*dlt[i,r]; one s per block (256 blocks -> good occupancy)
__global__ void kE(const float* __restrict__ dlt, const float* __restrict__ toep, int Kc) {
    __shared__ float st[256];
    int r = threadIdx.x, s = blockIdx.x;
    if (r < Kc) st[r] = toep[r];
    __syncthreads();
    int pad = (Kc - 1) >> 1;
    int lo = s - pad; if (lo < 0) lo = 0;
    int hi = s - pad + Kc - 1; if (hi > Rk - 1) hi = Rk - 1;
    float a = 0.f;
    #pragma unroll 4
    for (int i = lo; i <= hi; i++) a += st[i - s + pad] * dlt[(size_t)i * Rk + r];
    g_E[(size_t)s * Rk + r] = a;
}

__global__ void kCab() {
    __shared__ float sm[256];
    int s = blockIdx.x, r = threadIdx.x;
    float e = g_E[(size_t)s * Rk + r];
    float ca = blockReduce256(g_pg[r] * e, sm);
    float cb = blockReduce256(g_pb[r] * e, sm);
    if (r == 0) { g_cA[s] = ca; g_cB[s] = cb; }
}

// A'^T[s,d] = gamma[d] * sum_r P[d,r] E[s,r] -> g_BT1 (fp16)
__global__ __launch_bounds__(256) void kAp(const float* __restrict__ P,
                                           const float* __restrict__ gamma) {
    __shared__ float Ps[16][64];
    __shared__ float Es[16][64];
    int dBase = blockIdx.y * 64, sBase = blockIdx.x * 64;
    int t = threadIdx.x;
    int ty = t >> 4, tx = t & 15;
    float acc[4][4] = {};
    for (int k0 = 0; k0 < Rk; k0 += 16) {
        {
            int m = t >> 2, kq = (t & 3) * 4;
            float4 v = *(const float4*)&P[(size_t)(dBase + m) * Rk + k0 + kq];
            Ps[kq + 0][m] = v.x; Ps[kq + 1][m] = v.y; Ps[kq + 2][m] = v.z; Ps[kq + 3][m] = v.w;
        }
        {
            int n = t >> 2, kq = (t & 3) * 4;
            float4 v = *(const float4*)&g_E[(size_t)(sBase + n) * Rk + k0 + kq];
            Es[kq + 0][n] = v.x; Es[kq + 1][n] = v.y; Es[kq + 2][n] = v.z; Es[kq + 3][n] = v.w;
        }
        __syncthreads();
        #pragma unroll
        for (int k = 0; k < 16; k++) {
            float a[4], b[4];
            #pragma unroll
            for (int i = 0; i < 4; i++) a[i] = Ps[k][ty * 4 + i];
            #pragma unroll
            for (int j = 0; j < 4; j++) b[j] = Es[k][tx * 4 + j];
            #pragma unroll
            for (int i = 0; i < 4; i++)
                #pragma unroll
                for (int j = 0; j < 4; j++) acc[i][j] += a[i] * b[j];
        }
        __syncthreads();
    }
    #pragma unroll
    for (int i = 0; i < 4; i++) {
        int d = dBase + ty * 4 + i;
        float g = gamma[d];
        #pragma unroll
        for (int j = 0; j < 4; j++) {
            int s = sBase + tx * 4 + j;
            g_BT1[(size_t)s * Dk + d] = __float2half_rn(g * acc[i][j]);
        }
    }
}

// WqT[d,r] = fp16(Wq[r,d])
__global__ void kWqT(const float* __restrict__ Wq) {
    __shared__ float tile[32][33];
    int bx = blockIdx.x, by = blockIdx.y;
    int tx = threadIdx.x & 31, ty8 = threadIdx.x >> 5;
    #pragma unroll
    for (int i = 0; i < 32; i += 8)
        tile[ty8 + i][tx] = Wq[(size_t)(by * 32 + ty8 + i) * Dk + bx * 32 + tx];
    __syncthreads();
    #pragma unroll
    for (int i = 0; i < 32; i += 8)
        g_WqT[(size_t)(bx * 32 + ty8 + i) * Rk + by * 32 + tx] =
            __float2half_rn(tile[tx][ty8 + i]);
}

// G[l] = sigmoid(g_logit[..]) * scale[l]
__global__ void kScale(const float* __restrict__ phib, const float* __restrict__ glog,
                       const int* __restrict__ step_p, int glen) {
    int w = threadIdx.x >> 5, lane = threadIdx.x & 31;
    int l = blockIdx.x * 8 + w;
    const float PI_F = 3.14159274101257324f;
    float base = PI_F * ((float)l + 0.5f);
    float c1 = 0.f, c2 = 0.f;
    #pragma unroll
    for (int j = 0; j < 8; j++) {
        int r = lane + 32 * j;
        c1 += cosf((base * (float)r) / (float)Lk);
        c2 += phib[(size_t)l * Rk + r];
    }
    float c3 = (lane < Bk) ? g_feat[(size_t)lane * Lk + l] : 0.f;
    #pragma unroll
    for (int o = 16; o > 0; o >>= 1) {
        c1 += __shfl_xor_sync(0xffffffffu, c1, o);
        c2 += __shfl_xor_sync(0xffffffffu, c2, o);
        c3 += __shfl_xor_sync(0xffffffffu, c3, o);
    }
    if (lane == 0) {
        int step = *step_p;
        float det_scale = fminf((float)((double)step / 2000.0), 1.0f);
        float scale = det_scale * (c1 / (float)Rk) + (c2 / (float)Rk)
                    + (c3 / (float)Bk) * (g_consts[2] / (float)Rk);
        int gi = l / (Dk / glen);
        float gs = 1.0f / (1.0f + expf(-glog[gi]));
        g_G[l] = gs * scale;
    }
}

// ================= fp16 mma GEMM 1 =================
// U = (X @ A')*rstd + nmr*cA + cB ; M=16384, N=256, K=2048. Fused LN stats.
// grid 128 CTAs (X read once), 512 threads, CTA tile 128x256, BK=16.
// Warps 0-7 stage A (fp32->fp16 + stats), warps 8-15 stage B (cp.async). All compute.
#define NT1 (Dk / 16)

__global__ __launch_bounds__(512) void kGemm1MMA(const float* __restrict__ X,
                                                 const float* __restrict__ gamma) {
    __shared__ __align__(16) __half As[2][128 * 24];
    __shared__ __align__(16) __half Bs[2][256 * 24];
    __shared__ float s_gam[Dk];
    __shared__ float s_rstd[128], s_nmr[128];

    int t = threadIdx.x, w = t >> 5, lane = t & 31, g = lane >> 2, tg = lane & 3;
    int rowBase = blockIdx.x * 128;
    int m0w = (w >> 3) * 64, n0w = (w & 7) * 32;

    for (int i = t; i < Dk / 4; i += 512)
        ((float4*)s_gam)[i] = ((const float4*)gamma)[i];

    uint32_t sA[2] = { smem_u32(As[0]), smem_u32(As[1]) };
    uint32_t sB[2] = { smem_u32(Bs[0]), smem_u32(Bs[1]) };
    uint32_t aOff = (uint32_t)((m0w + (lane & 15)) * 48 + (lane >> 4) * 16);
    uint32_t bOff = (uint32_t)((n0w + (lane & 7) + ((lane >> 4) << 3)) * 48
                               + ((lane >> 3) & 1) * 16);

    int lr = t >> 1, h = t & 1;           // A staging: row, 8-float half-chunk
    int t2 = t & 255;                      // B staging row (warps 8-15)
    const float4* Xr = (const float4*)(X + (size_t)(rowBase + lr) * Dk);
    const __half* Bsrc = g_BT1 + (size_t)t2 * Dk;

    float acc[4][4][4] = {};
    float s0 = 0.f, s20 = 0.f, sg0 = 0.f;

    __syncthreads();  // gamma visible

    // prologue: tile 0
    if (t >= 256) {
        cp16(Bs[0] + t2 * 24, Bsrc);
        cp16(Bs[0] + t2 * 24 + 8, Bsrc + 8);
        CP_COMMIT();
    } else {
        float4 q0 = Xr[h * 2], q1 = Xr[h * 2 + 1];
        float4 g0 = ((const float4*)s_gam)[h * 2], g1 = ((const float4*)s_gam)[h * 2 + 1];
        s0  += (q0.x + q0.y) + (q0.z + q0.w) + (q1.x + q1.y) + (q1.z + q1.w);
        s20 += q0.x*q0.x + q0.y*q0.y + q0.z*q0.z + q0.w*q0.w
             + q1.x*q1.x + q1.y*q1.y + q1.z*q1.z + q1.w*q1.w;
        sg0 += g0.x*q0.x + g0.y*q0.y + g0.z*q0.z + g0.w*q0.w
             + g1.x*q1.x + g1.y*q1.y + g1.z*q1.z + g1.w*q1.w;
        uint4 pk = { h2pack(q0.x, q0.y), h2pack(q0.z, q0.w),
                     h2pack(q1.x, q1.y), h2pack(q1.z, q1.w) };
        *(uint4*)(As[0] + lr * 24 + h * 8) = pk;
    }
    CP_WAIT0();
    __syncthreads();

    #pragma unroll 1
    for (int tt = 0; tt < NT1; ++tt) {
        int buf = tt & 1, nbuf = buf ^ 1;
        float4 q0, q1;
        if (tt + 1 < NT1) {
            int kq = (tt + 1) * 4;
            if (t >= 256) {
                const __half* src = Bsrc + (tt + 1) * 16;
                cp16(Bs[nbuf] + t2 * 24, src);
                cp16(Bs[nbuf] + t2 * 24 + 8, src + 8);
                CP_COMMIT();
            } else {
                q0 = Xr[kq + h * 2];
                q1 = Xr[kq + h * 2 + 1];
            }
        }
        // compute tile tt
        {
            uint32_t af[4][4], bf[4][2];
            #pragma unroll
            for (int mi = 0; mi < 4; ++mi)
                LDSM4(af[mi][0], af[mi][1], af[mi][2], af[mi][3],
                      sA[buf] + aOff + mi * 16 * 48);
            #pragma unroll
            for (int ni2 = 0; ni2 < 2; ++ni2) {
                uint32_t r0, r1, r2, r3;
                LDSM4(r0, r1, r2, r3, sB[buf] + bOff + ni2 * 16 * 48);
                bf[ni2 * 2][0] = r0; bf[ni2 * 2][1] = r1;
                bf[ni2 * 2 + 1][0] = r2; bf[ni2 * 2 + 1][1] = r3;
            }
            #pragma unroll
            for (int mi = 0; mi < 4; ++mi)
                #pragma unroll
                for (int ni = 0; ni < 4; ++ni)
                    MMAF16(acc[mi][ni], af[mi], bf[ni]);
        }
        if (tt + 1 < NT1 && t < 256) {
            int kq = (tt + 1) * 4;
            float4 g0 = ((const float4*)s_gam)[kq + h * 2];
            float4 g1 = ((const float4*)s_gam)[kq + h * 2 + 1];
            s0  += (q0.x + q0.y) + (q0.z + q0.w) + (q1.x + q1.y) + (q1.z + q1.w);
            s20 += q0.x*q0.x + q0.y*q0.y + q0.z*q0.z + q0.w*q0.w
                 + q1.x*q1.x + q1.y*q1.y + q1.z*q1.z + q1.w*q1.w;
            sg0 += g0.x*q0.x + g0.y*q0.y + g0.z*q0.z + g0.w*q0.w
                 + g1.x*q1.x + g1.y*q1.y + g1.z*q1.z + g1.w*q1.w;
            uint4 pk = { h2pack(q0.x, q0.y), h2pack(q0.z, q0.w),
                         h2pack(q1.x, q1.y), h2pack(q1.z, q1.w) };
            *(uint4*)(As[nbuf] + lr * 24 + h * 8) = pk;
        }
        CP_WAIT0();
        __syncthreads();
    }

    // LN stats: 2 staging threads per row
    if (t < 256) {
        s0  += __shfl_xor_sync(0xffffffffu, s0, 1);
        s20 += __shfl_xor_sync(0xffffffffu, s20, 1);
        sg0 += __shfl_xor_sync(0xffffffffu, sg0, 1);
        if (h == 0) {
            float C0 = g_consts[0], C1 = g_consts[1];
            float mean = s0 * (1.f / Dk);
            float var = s20 * (1.f / Dk) - mean * mean;
            float rstd = rsqrtf(var + 1e-5f);
            s_rstd[lr] = rstd;
            s_nmr[lr] = -mean * rstd;
            g_feat[rowBase + lr] = (sg0 - mean * C0) * rstd * (1.f / Dk) + C1 * (1.f / Dk);
        }
    }
    __syncthreads();

    // epilogue -> g_U (fp16)
    #pragma unroll
    for (int ni = 0; ni < 4; ++ni) {
        int cg = n0w + ni * 8 + 2 * tg;
        float ca0 = g_cA[cg], ca1 = g_cA[cg + 1];
        float cb0 = g_cB[cg], cb1 = g_cB[cg + 1];
        #pragma unroll
        for (int mi = 0; mi < 4; ++mi) {
            int r1 = m0w + mi * 16 + g;
            float rs1 = s_rstd[r1], nm1 = s_nmr[r1];
            float rs2 = s_rstd[r1 + 8], nm2 = s_nmr[r1 + 8];
            uint32_t o1 = h2pack(acc[mi][ni][0] * rs1 + nm1 * ca0 + cb0,
                                 acc[mi][ni][1] * rs1 + nm1 * ca1 + cb1);
            uint32_t o2 = h2pack(acc[mi][ni][2] * rs2 + nm2 * ca0 + cb0,
                                 acc[mi][ni][3] * rs2 + nm2 * ca1 + cb1);
            *(uint32_t*)(g_U + (size_t)(rowBase + r1) * Rk + cg) = o1;
            *(uint32_t*)(g_U + (size_t)(rowBase + r1 + 8) * Rk + cg) = o2;
        }
    }
}

// ================= fp16 mma GEMM 2 =================
// out = G[d]*(U @ Wq + bq) ; M=16384, N=2048, K=256. grid (16,128), 256 thr,
// CTA tile 128x128, warp tile 64x32, BK=16.
#define NT2 (Rk / 16)

__global__ __launch_bounds__(256) void kGemm2MMA(const float* __restrict__ bq,
                                                 float* __restrict__ out) {
    __shared__ __align__(16) __half As[2][128 * 24];
    __shared__ __align__(16) __half Bs[2][128 * 24];

    int t = threadIdx.x, w = t >> 5, lane = t & 31, g = lane >> 2, tg = lane & 3;
    int rowBase = blockIdx.y * 128, colBase = blockIdx.x * 128;
    int m0w = (w >> 2) * 64, n0w = (w & 3) * 32;

    uint32_t sA[2] = { smem_u32(As[0]), smem_u32(As[1]) };
    uint32_t sB[2] = { smem_u32(Bs[0]), smem_u32(Bs[1]) };
    uint32_t aOff = (uint32_t)((m0w + (lane & 15)) * 48 + (lane >> 4) * 16);
    uint32_t bOff = (uint32_t)((n0w + (lane & 7) + ((lane >> 4) << 3)) * 48
                               + ((lane >> 3) & 1) * 16);

    int lr = t >> 1, h = t & 1;
    const __half* Asrc = g_U + (size_t)(rowBase + lr) * Rk + h * 8;
    const __half* Bsrc = g_WqT + (size_t)(colBase + lr) * Rk + h * 8;

    float acc[4][4][4] = {};

    cp16(As[0] + lr * 24 + h * 8, Asrc);
    cp16(Bs[0] + lr * 24 + h * 8, Bsrc);
    CP_COMMIT();
    CP_WAIT0();
    __syncthreads();

    #pragma unroll 1
    for (int tt = 0; tt < NT2; ++tt) {
        int buf = tt & 1, nbuf = buf ^ 1;
        if (tt + 1 < NT2) {
            cp16(As[nbuf] + lr * 24 + h * 8, Asrc + (tt + 1) * 16);
            cp16(Bs[nbuf] + lr * 24 + h * 8, Bsrc + (tt + 1) * 16);
            CP_COMMIT();
        }
        {
            uint32_t af[4][4], bf[4][2];
            #pragma unroll
            for (int mi = 0; mi < 4; ++mi)
                LDSM4(af[mi][0], af[mi][1], af[mi][2], af[mi][3],
                      sA[buf] + aOff + mi * 16 * 48);
            #pragma unroll
            for (int ni2 = 0; ni2 < 2; ++ni2) {
                uint32_t r0, r1, r2, r3;
                LDSM4(r0, r1, r2, r3, sB[buf] + bOff + ni2 * 16 * 48);
                bf[ni2 * 2][0] = r0; bf[ni2 * 2][1] = r1;
                bf[ni2 * 2 + 1][0] = r2; bf[ni2 * 2 + 1][1] = r3;
            }
            #pragma unroll
            for (int mi = 0; mi < 4; ++mi)
                #pragma unroll
                for (int ni = 0; ni < 4; ++ni)
                    MMAF16(acc[mi][ni], af[mi], bf[ni]);
        }
        CP_WAIT0();
        __syncthreads();
    }

    #pragma unroll
    for (int ni = 0; ni < 4; ++ni) {
        int cg = colBase + n0w + ni * 8 + 2 * tg;
        float G0 = g_G[cg], G1 = g_G[cg + 1];
        float q0 = bq[cg], q1 = bq[cg + 1];
        #pragma unroll
        for (int mi = 0; mi < 4; ++mi) {
            int r1 = rowBase + m0w + mi * 16 + g;
            float2 o1, o2;
            o1.x = G0 * (acc[mi][ni][0] + q0);
            o1.y = G1 * (acc[mi][ni][1] + q1);
            o2.x = G0 * (acc[mi][ni][2] + q0);
            o2.y = G1 * (acc[mi][ni][3] + q1);
            *(float2*)&out[(size_t)r1 * Dk + cg] = o1;
            *(float2*)&out[(size_t)(r1 + 8) * Dk + cg] = o2;
        }
    }
}

// ---------------- launch ----------------
extern "C" void kernel_launch(void* const* d_in, const int* in_sizes, int n_in,
                              void* d_out, int out_size) {
    const float* x     = (const float*)d_in[0];
    const float* gamma = (const float*)d_in[1];
    const float* beta  = (const float*)d_in[2];
    const float* P     = (const float*)d_in[3];
    const float* dlt   = (const float*)d_in[4];
    const float* phiw  = (const float*)d_in[5];
    const float* phib  = (const float*)d_in[6];
    const float* toep  = (const float*)d_in[7];
    const float* Wq    = (const float*)d_in[8];
    const float* bq    = (const float*)d_in[9];
    const float* glog  = (const float*)d_in[10];
    const int*   step  = (const int*)d_in[11];
    int Kc   = in_sizes[7];
    int glen = in_sizes[10];

    kConst<<<1, 256>>>(gamma, beta, phiw);
    kPgb1<<<32, 256>>>(P, gamma, beta);
    kPgb2<<<1, 256>>>();
    kE<<<256, 256>>>(dlt, toep, Kc);
    kCab<<<256, 256>>>();
    kAp<<<dim3(4, 32), 256>>>(P, gamma);
    kWqT<<<dim3(64, 8), 256>>>(Wq);
    kGemm1MMA<<<128, 512>>>(x, gamma);
    kScale<<<256, 256>>>(phib, glog, step, glen);
    kGemm2MMA<<<dim3(16, 128), 256>>>(bq, (float*)d_out);
}

// round 5
// speedup vs baseline: 4.6782x; 1.2476x over previous
#include <cuda_runtime.h>
#include <cuda_fp16.h>
#include <cstdint>
#include <math.h>

#define Bk 8
#define Lk 2048
#define Dk 2048
#define Rk 256
#define BLk (Bk * Lk)   // 16384 rows

// ---------------- device scratch ----------------
static __device__ float g_C[Rk * Rk];                 // Toeplitz matrix C[s,i]
static __device__ float g_E[Rk * Rk];                 // E = C @ dlt       (256x256)
static __device__ __half g_BT1[Rk * Dk];              // A'^T fp16         (256x2048)
static __device__ __half g_WqT[Dk * Rk];              // Wq^T fp16         (2048x256)
static __device__ __half g_U[(size_t)BLk * Rk];       // z_mixed fp16
static __device__ float g_feat[BLk];
static __device__ float g_pg[Rk], g_pb[Rk];
static __device__ float g_cA[Rk], g_cB[Rk];
static __device__ float g_G[Dk];
static __device__ float g_consts[4];
static __device__ float g_pgp[32 * Rk], g_pbp[32 * Rk];

// ---------------- helpers ----------------
__device__ __forceinline__ uint32_t smem_u32(const void* p) {
    uint32_t a;
    asm("{ .reg .u64 t; cvta.to.shared.u64 t, %1; cvt.u32.u64 %0, t; }" : "=r"(a) : "l"(p));
    return a;
}
__device__ __forceinline__ void cp16(void* dst, const void* src) {
    uint32_t d = smem_u32(dst);
    asm volatile("cp.async.cg.shared.global [%0], [%1], 16;" :: "r"(d), "l"(src) : "memory");
}
#define CP_COMMIT() asm volatile("cp.async.commit_group;" ::: "memory")
#define CP_WAIT0()  asm volatile("cp.async.wait_group 0;" ::: "memory")
#define CP_WAIT1()  asm volatile("cp.async.wait_group 1;" ::: "memory")

#define LDSM4(r0, r1, r2, r3, addr) \
    asm volatile("ldmatrix.sync.aligned.m8n8.x4.shared.b16 {%0,%1,%2,%3}, [%4];" \
        : "=r"(r0), "=r"(r1), "=r"(r2), "=r"(r3) : "r"(addr))

#define MMAF16(c, a, b) \
    asm volatile( \
        "mma.sync.aligned.m16n8k16.row.col.f32.f16.f16.f32 " \
        "{%0,%1,%2,%3},{%4,%5,%6,%7},{%8,%9},{%0,%1,%2,%3};" \
        : "+f"((c)[0]), "+f"((c)[1]), "+f"((c)[2]), "+f"((c)[3]) \
        : "r"((a)[0]), "r"((a)[1]), "r"((a)[2]), "r"((a)[3]), \
          "r"((b)[0]), "r"((b)[1]))

__device__ __forceinline__ uint32_t h2pack(float a, float b) {
    __half2 h = __floats2half2_rn(a, b);
    return *reinterpret_cast<uint32_t*>(&h);
}

__device__ __forceinline__ float blockReduce256(float v, float* sm) {
    int t = threadIdx.x;
    sm[t] = v;
    __syncthreads();
    #pragma unroll
    for (int off = 128; off > 0; off >>= 1) {
        if (t < off) sm[t] += sm[t + off];
        __syncthreads();
    }
    float r = sm[0];
    __syncthreads();
    return r;
}

// pad-40-halves row layout (80 bytes): ldmatrix phases conflict-free.
#define PADH 40
#define PADB 80

// ================= fused precompute 1 =================
// bid 0: consts; 1..32: pgb partials; 33..288: build C; 289..800: WqT transpose
__global__ __launch_bounds__(256) void kPre1(const float* __restrict__ gamma,
                                             const float* __restrict__ beta,
                                             const float* __restrict__ phiw,
                                             const float* __restrict__ P,
                                             const float* __restrict__ toep,
                                             const float* __restrict__ Wq, int Kc) {
    int bid = blockIdx.x, t = threadIdx.x;
    if (bid == 0) {
        __shared__ float sm[256];
        float a = 0.f, b = 0.f, c = 0.f;
        for (int j = t; j < Dk; j += 256) { a += gamma[j]; b += beta[j]; }
        for (int j = t; j < Rk; j += 256) { c += phiw[j]; }
        float A = blockReduce256(a, sm);
        float B = blockReduce256(b, sm);
        float C = blockReduce256(c, sm);
        if (t == 0) { g_consts[0] = A; g_consts[1] = B; g_consts[2] = C; }
    } else if (bid <= 32) {
        int chunk = bid - 1;
        float ag = 0.f, ab = 0.f;
        #pragma unroll 4
        for (int j = 0; j < 64; j++) {
            int d = chunk * 64 + j;
            float p = P[(size_t)d * Rk + t];
            ag += gamma[d] * p;
            ab += beta[d] * p;
        }
        g_pgp[chunk * Rk + t] = ag;
        g_pbp[chunk * Rk + t] = ab;
    } else if (bid <= 288) {
        int s = bid - 33;
        int pad = (Kc - 1) >> 1;
        int idx = t - s + pad;
        g_C[s * Rk + t] = (idx >= 0 && idx < Kc) ? toep[idx] : 0.f;
    } else {
        int id = bid - 289;
        int bx = id & 63, by = id >> 6;
        __shared__ float tile[32][33];
        int tx = t & 31, ty8 = t >> 5;
        #pragma unroll
        for (int i = 0; i < 32; i += 8)
            tile[ty8 + i][tx] = Wq[(size_t)(by * 32 + ty8 + i) * Dk + bx * 32 + tx];
        __syncthreads();
        #pragma unroll
        for (int i = 0; i < 32; i += 8)
            g_WqT[(size_t)(bx * 32 + ty8 + i) * Rk + by * 32 + tx] =
                __float2half_rn(tile[tx][ty8 + i]);
    }
}

// ================= kEg: E = C @ dlt (fp32 64x64 tiles) + pgb2 reduce =================
__global__ __launch_bounds__(256) void kEg(const float* __restrict__ dlt) {
    int bid = blockIdx.x, t = threadIdx.x;
    if (bid == 16) {  // pgb2
        float a = 0.f, b = 0.f;
        #pragma unroll
        for (int c = 0; c < 32; c++) { a += g_pgp[c * Rk + t]; b += g_pbp[c * Rk + t]; }
        g_pg[t] = a;
        g_pb[t] = b;
        return;
    }
    __shared__ float Cs[16][66];
    __shared__ float Ds[16][68];
    int bx = bid & 3, by = bid >> 2;
    int sBase = by * 64, rBase = bx * 64;
    int ty = t >> 4, tx = t & 15;
    float acc[4][4] = {};
    for (int k0 = 0; k0 < Rk; k0 += 16) {
        {
            int m = t >> 2, kq = (t & 3) * 4;
            float4 v = *(const float4*)&g_C[(size_t)(sBase + m) * Rk + k0 + kq];
            Cs[kq + 0][m] = v.x; Cs[kq + 1][m] = v.y; Cs[kq + 2][m] = v.z; Cs[kq + 3][m] = v.w;
        }
        {
            int kk = t >> 4, n4 = (t & 15) * 4;
            float4 v = *(const float4*)&dlt[(size_t)(k0 + kk) * Rk + rBase + n4];
            *(float4*)&Ds[kk][n4] = v;
        }
        __syncthreads();
        #pragma unroll
        for (int k = 0; k < 16; k++) {
            float a[4], b[4];
            #pragma unroll
            for (int i = 0; i < 4; i++) a[i] = Cs[k][ty * 4 + i];
            #pragma unroll
            for (int j = 0; j < 4; j++) b[j] = Ds[k][tx * 4 + j];
            #pragma unroll
            for (int i = 0; i < 4; i++)
                #pragma unroll
                for (int j = 0; j < 4; j++) acc[i][j] += a[i] * b[j];
        }
        __syncthreads();
    }
    #pragma unroll
    for (int i = 0; i < 4; i++)
        #pragma unroll
        for (int j = 0; j < 4; j++)
            g_E[(size_t)(sBase + ty * 4 + i) * Rk + rBase + tx * 4 + j] = acc[i][j];
}

// ================= kApCab: A'^T (fp16) + cA/cB =================
// bid 0..127: kAp tile; bid 128..383: cA/cB row s = bid-128
__global__ __launch_bounds__(256) void kApCab(const float* __restrict__ P,
                                              const float* __restrict__ gamma) {
    int bid = blockIdx.x, t = threadIdx.x;
    if (bid >= 128) {
        __shared__ float sm[256];
        int s = bid - 128;
        float e = g_E[(size_t)s * Rk + t];
        float ca = blockReduce256(g_pg[t] * e, sm);
        float cb = blockReduce256(g_pb[t] * e, sm);
        if (t == 0) { g_cA[s] = ca; g_cB[s] = cb; }
        return;
    }
    __shared__ float Ps[16][64];
    __shared__ float Es[16][64];
    int bx = bid & 3, by = bid >> 2;
    int dBase = by * 64, sBase = bx * 64;
    int ty = t >> 4, tx = t & 15;
    float acc[4][4] = {};
    for (int k0 = 0; k0 < Rk; k0 += 16) {
        {
            int m = t >> 2, kq = (t & 3) * 4;
            float4 v = *(const float4*)&P[(size_t)(dBase + m) * Rk + k0 + kq];
            Ps[kq + 0][m] = v.x; Ps[kq + 1][m] = v.y; Ps[kq + 2][m] = v.z; Ps[kq + 3][m] = v.w;
        }
        {
            int n = t >> 2, kq = (t & 3) * 4;
            float4 v = *(const float4*)&g_E[(size_t)(sBase + n) * Rk + k0 + kq];
            Es[kq + 0][n] = v.x; Es[kq + 1][n] = v.y; Es[kq + 2][n] = v.z; Es[kq + 3][n] = v.w;
        }
        __syncthreads();
        #pragma unroll
        for (int k = 0; k < 16; k++) {
            float a[4], b[4];
            #pragma unroll
            for (int i = 0; i < 4; i++) a[i] = Ps[k][ty * 4 + i];
            #pragma unroll
            for (int j = 0; j < 4; j++) b[j] = Es[k][tx * 4 + j];
            #pragma unroll
            for (int i = 0; i < 4; i++)
                #pragma unroll
                for (int j = 0; j < 4; j++) acc[i][j] += a[i] * b[j];
        }
        __syncthreads();
    }
    #pragma unroll
    for (int i = 0; i < 4; i++) {
        int d = dBase + ty * 4 + i;
        float g = gamma[d];
        #pragma unroll
        for (int j = 0; j < 4; j++) {
            int s = sBase + tx * 4 + j;
            g_BT1[(size_t)s * Dk + d] = __float2half_rn(g * acc[i][j]);
        }
    }
}

// G[l] = sigmoid(g_logit[..]) * scale[l]
__global__ void kScale(const float* __restrict__ phib, const float* __restrict__ glog,
                       const int* __restrict__ step_p, int glen) {
    int w = threadIdx.x >> 5, lane = threadIdx.x & 31;
    int l = blockIdx.x * 8 + w;
    const float PI_F = 3.14159274101257324f;
    float base = PI_F * ((float)l + 0.5f);
    float c1 = 0.f, c2 = 0.f;
    #pragma unroll
    for (int j = 0; j < 8; j++) {
        int r = lane + 32 * j;
        c1 += cosf((base * (float)r) / (float)Lk);
        c2 += phib[(size_t)l * Rk + r];
    }
    float c3 = (lane < Bk) ? g_feat[(size_t)lane * Lk + l] : 0.f;
    #pragma unroll
    for (int o = 16; o > 0; o >>= 1) {
        c1 += __shfl_xor_sync(0xffffffffu, c1, o);
        c2 += __shfl_xor_sync(0xffffffffu, c2, o);
        c3 += __shfl_xor_sync(0xffffffffu, c3, o);
    }
    if (lane == 0) {
        int step = *step_p;
        float det_scale = fminf((float)((double)step / 2000.0), 1.0f);
        float scale = det_scale * (c1 / (float)Rk) + (c2 / (float)Rk)
                    + (c3 / (float)Bk) * (g_consts[2] / (float)Rk);
        int gi = l / (Dk / glen);
        float gs = 1.0f / (1.0f + expf(-glog[gi]));
        g_G[l] = gs * scale;
    }
}

// ================= fp16 mma GEMM 1 =================
// U = (X @ A')*rstd + nmr*cA + cB; M=16384, N=256, K=2048. BK=32, NT=64,
// grid 128 CTAs (X read once), 512 thr. Warps 0-7 stage A (fp32->fp16 + LN stats),
// warps 8-15 stage B (cp.async). All 16 warps compute 64x32 warp tiles.
#define NT1 64
#define SM1_AS0   0
#define SM1_AS1   10240
#define SM1_BS0   20480
#define SM1_BS1   40960
#define SM1_GAM   61440
#define SM1_RSTD  69632
#define SM1_NMR   70144
#define SM1_TOTAL 70656

__global__ __launch_bounds__(512) void kGemm1MMA(const float* __restrict__ X,
                                                 const float* __restrict__ gamma) {
    extern __shared__ char sm1[];
    __half* As[2] = { (__half*)(sm1 + SM1_AS0), (__half*)(sm1 + SM1_AS1) };
    __half* Bs[2] = { (__half*)(sm1 + SM1_BS0), (__half*)(sm1 + SM1_BS1) };
    float* s_gam  = (float*)(sm1 + SM1_GAM);
    float* s_rstd = (float*)(sm1 + SM1_RSTD);
    float* s_nmr  = (float*)(sm1 + SM1_NMR);

    int t = threadIdx.x, w = t >> 5, lane = t & 31, g = lane >> 2, tg = lane & 3;
    int rowBase = blockIdx.x * 128;
    int m0w = (w >> 3) * 64, n0w = (w & 7) * 32;

    for (int i = t; i < Dk / 4; i += 512)
        ((float4*)s_gam)[i] = ((const float4*)gamma)[i];

    uint32_t sA[2] = { smem_u32(As[0]), smem_u32(As[1]) };
    uint32_t sB[2] = { smem_u32(Bs[0]), smem_u32(Bs[1]) };
    uint32_t aBase = (uint32_t)((m0w + (lane & 15)) * PADB + (lane >> 4) * 16);
    uint32_t bBase = (uint32_t)((n0w + (lane & 7) + ((lane >> 4) << 3)) * PADB
                                + ((lane >> 3) & 1) * 16);

    int lr = t >> 1, h = t & 1;   // A stagers: row, 16-float half
    int t2 = t & 255;             // B stagers row
    const float4* Xr = (const float4*)(X + (size_t)(rowBase + lr) * Dk);
    const __half* Bsrc = g_BT1 + (size_t)t2 * Dk;

    float acc[4][4][4] = {};
    float s0 = 0.f, s20 = 0.f, sg0 = 0.f;

    __syncthreads();  // gamma visible

    // prologue: tile 0
    if (t >= 256) {
        #pragma unroll
        for (int q = 0; q < 4; q++)
            cp16(Bs[0] + t2 * PADH + q * 8, Bsrc + q * 8);
        CP_COMMIT();
    } else {
        float4 q[4];
        #pragma unroll
        for (int j = 0; j < 4; j++) q[j] = Xr[h * 4 + j];
        #pragma unroll
        for (int j = 0; j < 4; j++) {
            float4 gv = ((const float4*)s_gam)[h * 4 + j];
            s0  += (q[j].x + q[j].y) + (q[j].z + q[j].w);
            s20 += q[j].x*q[j].x + q[j].y*q[j].y + q[j].z*q[j].z + q[j].w*q[j].w;
            sg0 += gv.x*q[j].x + gv.y*q[j].y + gv.z*q[j].z + gv.w*q[j].w;
        }
        uint4 p0 = { h2pack(q[0].x,q[0].y), h2pack(q[0].z,q[0].w),
                     h2pack(q[1].x,q[1].y), h2pack(q[1].z,q[1].w) };
        uint4 p1 = { h2pack(q[2].x,q[2].y), h2pack(q[2].z,q[2].w),
                     h2pack(q[3].x,q[3].y), h2pack(q[3].z,q[3].w) };
        *(uint4*)(As[0] + lr * PADH + h * 16)     = p0;
        *(uint4*)(As[0] + lr * PADH + h * 16 + 8) = p1;
    }
    CP_WAIT0();
    __syncthreads();

    #pragma unroll 1
    for (int tt = 0; tt < NT1; ++tt) {
        int buf = tt & 1, nbuf = buf ^ 1;
        float4 q[4];
        if (tt + 1 < NT1) {
            int kq = (tt + 1) * 8;
            if (t >= 256) {
                const __half* src = Bsrc + (tt + 1) * 32;
                #pragma unroll
                for (int qq = 0; qq < 4; qq++)
                    cp16(Bs[nbuf] + t2 * PADH + qq * 8, src + qq * 8);
                CP_COMMIT();
            } else {
                #pragma unroll
                for (int j = 0; j < 4; j++) q[j] = Xr[kq + h * 4 + j];
            }
        }
        // compute tile tt (two k16 steps)
        #pragma unroll
        for (int ks = 0; ks < 2; ++ks) {
            uint32_t af[4][4], bf[4][2];
            #pragma unroll
            for (int mi = 0; mi < 4; ++mi)
                LDSM4(af[mi][0], af[mi][1], af[mi][2], af[mi][3],
                      sA[buf] + aBase + mi * 16 * PADB + ks * 32);
            #pragma unroll
            for (int ni2 = 0; ni2 < 2; ++ni2) {
                uint32_t r0, r1, r2, r3;
                LDSM4(r0, r1, r2, r3, sB[buf] + bBase + ni2 * 16 * PADB + ks * 32);
                bf[ni2 * 2][0] = r0; bf[ni2 * 2][1] = r1;
                bf[ni2 * 2 + 1][0] = r2; bf[ni2 * 2 + 1][1] = r3;
            }
            #pragma unroll
            for (int mi = 0; mi < 4; ++mi)
                #pragma unroll
                for (int ni = 0; ni < 4; ++ni)
                    MMAF16(acc[mi][ni], af[mi], bf[ni]);
        }
        if (tt + 1 < NT1 && t < 256) {
            int kq = (tt + 1) * 8;
            #pragma unroll
            for (int j = 0; j < 4; j++) {
                float4 gv = ((const float4*)s_gam)[kq + h * 4 + j];
                s0  += (q[j].x + q[j].y) + (q[j].z + q[j].w);
                s20 += q[j].x*q[j].x + q[j].y*q[j].y + q[j].z*q[j].z + q[j].w*q[j].w;
                sg0 += gv.x*q[j].x + gv.y*q[j].y + gv.z*q[j].z + gv.w*q[j].w;
            }
            uint4 p0 = { h2pack(q[0].x,q[0].y), h2pack(q[0].z,q[0].w),
                         h2pack(q[1].x,q[1].y), h2pack(q[1].z,q[1].w) };
            uint4 p1 = { h2pack(q[2].x,q[2].y), h2pack(q[2].z,q[2].w),
                         h2pack(q[3].x,q[3].y), h2pack(q[3].z,q[3].w) };
            *(uint4*)(As[nbuf] + lr * PADH + h * 16)     = p0;
            *(uint4*)(As[nbuf] + lr * PADH + h * 16 + 8) = p1;
        }
        CP_WAIT0();
        __syncthreads();
    }

    // LN stats: 2 staging threads per row
    if (t < 256) {
        s0  += __shfl_xor_sync(0xffffffffu, s0, 1);
        s20 += __shfl_xor_sync(0xffffffffu, s20, 1);
        sg0 += __shfl_xor_sync(0xffffffffu, sg0, 1);
        if (h == 0) {
            float C0 = g_consts[0], C1 = g_consts[1];
            float mean = s0 * (1.f / Dk);
            float var = s20 * (1.f / Dk) - mean * mean;
            float rstd = rsqrtf(var + 1e-5f);
            s_rstd[lr] = rstd;
            s_nmr[lr] = -mean * rstd;
            g_feat[rowBase + lr] = (sg0 - mean * C0) * rstd * (1.f / Dk) + C1 * (1.f / Dk);
        }
    }
    __syncthreads();

    // epilogue -> g_U (fp16)
    #pragma unroll
    for (int ni = 0; ni < 4; ++ni) {
        int cg = n0w + ni * 8 + 2 * tg;
        float ca0 = g_cA[cg], ca1 = g_cA[cg + 1];
        float cb0 = g_cB[cg], cb1 = g_cB[cg + 1];
        #pragma unroll
        for (int mi = 0; mi < 4; ++mi) {
            int r1 = m0w + mi * 16 + g;
            float rs1 = s_rstd[r1], nm1 = s_nmr[r1];
            float rs2 = s_rstd[r1 + 8], nm2 = s_nmr[r1 + 8];
            uint32_t o1 = h2pack(acc[mi][ni][0] * rs1 + nm1 * ca0 + cb0,
                                 acc[mi][ni][1] * rs1 + nm1 * ca1 + cb1);
            uint32_t o2 = h2pack(acc[mi][ni][2] * rs2 + nm2 * ca0 + cb0,
                                 acc[mi][ni][3] * rs2 + nm2 * ca1 + cb1);
            *(uint32_t*)(g_U + (size_t)(rowBase + r1) * Rk + cg) = o1;
            *(uint32_t*)(g_U + (size_t)(rowBase + r1 + 8) * Rk + cg) = o2;
        }
    }
}

// ================= fp16 mma GEMM 2 =================
// out = G[d]*(U @ Wq + bq); M=16384, N=2048, K=256. grid (16,128), 256 thr,
// CTA tile 128x128, warp tile 64x32, BK=32, NT=8, 3-stage cp.async pipeline.
#define NT2 8
#define SM2_STAGE 20480   // bytes per stage (A 10240 + B 10240)
#define SM2_TOTAL 61440

__global__ __launch_bounds__(256) void kGemm2MMA(const float* __restrict__ bq,
                                                 float* __restrict__ out) {
    extern __shared__ char sm2[];
    int t = threadIdx.x, w = t >> 5, lane = t & 31, g = lane >> 2, tg = lane & 3;
    int rowBase = blockIdx.y * 128, colBase = blockIdx.x * 128;
    int m0w = (w >> 2) * 64, n0w = (w & 3) * 32;

    uint32_t sBase0 = smem_u32(sm2);
    uint32_t aBase = (uint32_t)((m0w + (lane & 15)) * PADB + (lane >> 4) * 16);
    uint32_t bBase = 10240u + (uint32_t)((n0w + (lane & 7) + ((lane >> 4) << 3)) * PADB
                                         + ((lane >> 3) & 1) * 16);

    int lr = t >> 1, h = t & 1;
    const __half* Asrc = g_U + (size_t)(rowBase + lr) * Rk + h * 16;
    const __half* Bsrc = g_WqT + (size_t)(colBase + lr) * Rk + h * 16;

    float acc[4][4][4] = {};

    // issue stage: buffers at sm2 + st*SM2_STAGE
    #define G2_ISSUE(st, tt) do { \
        __half* A = (__half*)(sm2 + (st) * SM2_STAGE); \
        __half* B = (__half*)(sm2 + (st) * SM2_STAGE + 10240); \
        cp16(A + lr * PADH + h * 16,     Asrc + (tt) * 32); \
        cp16(A + lr * PADH + h * 16 + 8, Asrc + (tt) * 32 + 8); \
        cp16(B + lr * PADH + h * 16,     Bsrc + (tt) * 32); \
        cp16(B + lr * PADH + h * 16 + 8, Bsrc + (tt) * 32 + 8); \
        CP_COMMIT(); \
    } while (0)

    G2_ISSUE(0, 0);
    G2_ISSUE(1, 1);
    CP_WAIT1();
    __syncthreads();

    #pragma unroll 1
    for (int tt = 0; tt < NT2; ++tt) {
        int st = tt % 3;
        uint32_t sb = sBase0 + st * SM2_STAGE;
        #pragma unroll
        for (int ks = 0; ks < 2; ++ks) {
            uint32_t af[4][4], bf[4][2];
            #pragma unroll
            for (int mi = 0; mi < 4; ++mi)
                LDSM4(af[mi][0], af[mi][1], af[mi][2], af[mi][3],
                      sb + aBase + mi * 16 * PADB + ks * 32);
            #pragma unroll
            for (int ni2 = 0; ni2 < 2; ++ni2) {
                uint32_t r0, r1, r2, r3;
                LDSM4(r0, r1, r2, r3, sb + bBase + ni2 * 16 * PADB + ks * 32);
                bf[ni2 * 2][0] = r0; bf[ni2 * 2][1] = r1;
                bf[ni2 * 2 + 1][0] = r2; bf[ni2 * 2 + 1][1] = r3;
            }
            #pragma unroll
            for (int mi = 0; mi < 4; ++mi)
                #pragma unroll
                for (int ni = 0; ni < 4; ++ni)
                    MMAF16(acc[mi][ni], af[mi], bf[ni]);
        }
        if (tt + 2 < NT2) {
            G2_ISSUE((tt + 2) % 3, tt + 2);
            CP_WAIT1();
        } else if (tt + 1 < NT2) {
            CP_WAIT0();
        }
        __syncthreads();
    }

    #pragma unroll
    for (int ni = 0; ni < 4; ++ni) {
        int cg = colBase + n0w + ni * 8 + 2 * tg;
        float G0 = g_G[cg], G1 = g_G[cg + 1];
        float q0 = bq[cg], q1 = bq[cg + 1];
        #pragma unroll
        for (int mi = 0; mi < 4; ++mi) {
            int r1 = rowBase + m0w + mi * 16 + g;
            float2 o1, o2;
            o1.x = G0 * (acc[mi][ni][0] + q0);
            o1.y = G1 * (acc[mi][ni][1] + q1);
            o2.x = G0 * (acc[mi][ni][2] + q0);
            o2.y = G1 * (acc[mi][ni][3] + q1);
            *(float2*)&out[(size_t)r1 * Dk + cg] = o1;
            *(float2*)&out[(size_t)(r1 + 8) * Dk + cg] = o2;
        }
    }
}

// ---------------- launch ----------------
extern "C" void kernel_launch(void* const* d_in, const int* in_sizes, int n_in,
                              void* d_out, int out_size) {
    const float* x     = (const float*)d_in[0];
    const float* gamma = (const float*)d_in[1];
    const float* beta  = (const float*)d_in[2];
    const float* P     = (const float*)d_in[3];
    const float* dlt   = (const float*)d_in[4];
    const float* phiw  = (const float*)d_in[5];
    const float* phib  = (const float*)d_in[6];
    const float* toep  = (const float*)d_in[7];
    const float* Wq    = (const float*)d_in[8];
    const float* bq    = (const float*)d_in[9];
    const float* glog  = (const float*)d_in[10];
    const int*   step  = (const int*)d_in[11];
    int Kc   = in_sizes[7];
    int glen = in_sizes[10];

    cudaFuncSetAttribute(kGemm1MMA, cudaFuncAttributeMaxDynamicSharedMemorySize, SM1_TOTAL);
    cudaFuncSetAttribute(kGemm2MMA, cudaFuncAttributeMaxDynamicSharedMemorySize, SM2_TOTAL);

    kPre1<<<801, 256>>>(gamma, beta, phiw, P, toep, Wq, Kc);
    kEg<<<17, 256>>>(dlt);
    kApCab<<<384, 256>>>(P, gamma);
    kGemm1MMA<<<128, 512, SM1_TOTAL>>>(x, gamma);
    kScale<<<256, 256>>>(phib, glog, step, glen);
    kGemm2MMA<<<dim3(16, 128), 256, SM2_TOTAL>>>(bq, (float*)d_out);
}